// round 2
// baseline (speedup 1.0000x reference)
#include <cuda_runtime.h>
#include <cuda_bf16.h>

#define NN 512
#define TT 32
#define MMSG 31
#define EE 64
#define AA 64
#define NREL 201      // 200 relations + self-loop id 200
#define NTOK (NN*TT)  // 16384
#define PB 32         // tokens per projection pass

// ---- device scratch (no allocations allowed) ------------------------------
__device__ float g_self[NN * EE];            // h @ W_self
__device__ float g_q[NTOK * AA];             // 4 MB
__device__ float g_k[NTOK * AA];
__device__ float g_v[NTOK * AA];
__device__ int   g_cnt[2 * 256];             // [0..200] qv bins, [256..456] k bins
__device__ int   g_off[2 * 256];
__device__ int   g_cur[2 * 256];
__device__ int   g_list_qv[NTOK];
__device__ int   g_list_k[NTOK];

__device__ __forceinline__ void token_rels(int t, const int* mt, const int* rln,
                                           const int* rlm, int& rqv, int& rk) {
    int n = t >> 5, m = t & 31;
    if (m == 0) { rqv = rln[n]; rk = 200; }
    else { int i = n * MMSG + m - 1; rqv = rlm[i]; rk = mt[i]; }
}

// ---- 1. self projection: g_self = h @ W_self -------------------------------
__global__ __launch_bounds__(256) void k_self(const float* __restrict__ h,
                                              const float* __restrict__ W_self) {
    __shared__ float Ws[EE * EE];
    __shared__ float hb[16][EE];
    const int tid = threadIdx.x;
    const int n0 = blockIdx.x * 16;
    for (int i = tid; i < EE * EE / 4; i += 256)
        ((float4*)Ws)[i] = ((const float4*)W_self)[i];
    for (int i = tid; i < 16 * EE / 4; i += 256)
        ((float4*)&hb[0][0])[i] = ((const float4*)(h + n0 * EE))[i];
    __syncthreads();
    const int a = tid & 63, ng = tid >> 6;           // 4 node-slots
    #pragma unroll
    for (int s = 0; s < 4; s++) {
        const int nl = ng + s * 4;
        float acc = 0.f;
        #pragma unroll
        for (int e = 0; e < EE; e++) acc = fmaf(hb[nl][e], Ws[e * EE + a], acc);
        g_self[(n0 + nl) * EE + a] = acc;
    }
}

// ---- 2. bucketing -----------------------------------------------------------
__global__ void k_zero() {
    int i = threadIdx.x;
    g_cnt[i] = 0; g_cnt[256 + i] = 0;
}

__global__ void k_count(const int* __restrict__ mt, const int* __restrict__ rln,
                        const int* __restrict__ rlm) {
    int t = blockIdx.x * 512 + threadIdx.x;
    int rqv, rk; token_rels(t, mt, rln, rlm, rqv, rk);
    atomicAdd(&g_cnt[rqv], 1);
    atomicAdd(&g_cnt[256 + rk], 1);
}

__global__ void k_scan() {
    __shared__ int s0[256], s1[256];
    int tid = threadIdx.x;
    s0[tid] = (tid < NREL) ? g_cnt[tid] : 0;
    s1[tid] = (tid < NREL) ? g_cnt[256 + tid] : 0;
    __syncthreads();
    for (int d = 1; d < 256; d <<= 1) {
        int a0 = (tid >= d) ? s0[tid - d] : 0;
        int a1 = (tid >= d) ? s1[tid - d] : 0;
        __syncthreads();
        s0[tid] += a0; s1[tid] += a1;
        __syncthreads();
    }
    if (tid <= NREL) {
        int e0 = (tid == 0) ? 0 : s0[tid - 1];
        int e1 = (tid == 0) ? 0 : s1[tid - 1];
        g_off[tid] = e0; g_off[256 + tid] = e1;
        if (tid < NREL) { g_cur[tid] = e0; g_cur[256 + tid] = e1; }
    }
}

__global__ void k_scatter(const int* __restrict__ mt, const int* __restrict__ rln,
                          const int* __restrict__ rlm) {
    int t = blockIdx.x * 512 + threadIdx.x;
    int rqv, rk; token_rels(t, mt, rln, rlm, rqv, rk);
    int p0 = atomicAdd(&g_cur[rqv], 1);        g_list_qv[p0] = t;
    int p1 = atomicAdd(&g_cur[256 + rk], 1);   g_list_k[p1]  = t;
}

// ---- 3. bucketed relation projections ---------------------------------------
// blockIdx < 201: QV bucket r (weights Q[r], V[r]); else: K bucket r.
// 128 threads; register tile 4 a-cols x 4 tokens; PB=32 tokens per pass.
__global__ __launch_bounds__(128) void k_proj(const float* __restrict__ msg,
                                              const float* __restrict__ Q,
                                              const float* __restrict__ K,
                                              const float* __restrict__ V) {
    __shared__ float Ws1[EE * AA];
    __shared__ float Ws2[EE * AA];
    __shared__ float xb[EE][PB];
    __shared__ int   tlist[PB];

    const bool isK = blockIdx.x >= NREL;
    const int  r   = isK ? blockIdx.x - NREL : blockIdx.x;
    const int  bin = (isK ? 256 : 0) + r;
    const int  base = g_off[bin];
    const int  cnt  = g_off[bin + 1] - base;
    if (cnt == 0) return;
    const int tid = threadIdx.x;
    const int* __restrict__ list = isK ? g_list_k : g_list_qv;

    // stage weights
    {
        const float4* w1 = (const float4*)((isK ? K : Q) + (size_t)r * EE * AA);
        for (int i = tid; i < EE * AA / 4; i += 128) ((float4*)Ws1)[i] = w1[i];
        if (!isK) {
            const float4* w2 = (const float4*)(V + (size_t)r * EE * AA);
            for (int i = tid; i < EE * AA / 4; i += 128) ((float4*)Ws2)[i] = w2[i];
        }
    }

    const int ag = tid & 15;    // a-column group: a = ag*4
    const int tg = tid >> 4;    // token group: tokens tg*4 .. tg*4+3

    for (int p = 0; p < cnt; p += PB) {
        const int np = min(PB, cnt - p);
        __syncthreads();
        // stage x transposed into xb[e][tt] + token ids
        {
            const int tt = tid >> 2, qq = tid & 3;
            const bool valid = tt < np;
            int tok = valid ? list[base + p + tt] : 0;
            if (qq == 0) tlist[tt] = tok;
            const int n = tok >> 5, m = tok & 31;
            const float* xp = (m == 0) ? (g_self + n * EE)
                                       : (msg + (size_t)(n * MMSG + m - 1) * EE);
            #pragma unroll
            for (int j = 0; j < 4; j++) {
                const int e = qq * 16 + j * 4;
                float4 xv = valid ? *(const float4*)(xp + e) : make_float4(0.f,0.f,0.f,0.f);
                xb[e + 0][tt] = xv.x; xb[e + 1][tt] = xv.y;
                xb[e + 2][tt] = xv.z; xb[e + 3][tt] = xv.w;
            }
        }
        __syncthreads();

        if (!isK) {
            float a1[4][4], a2[4][4];
            #pragma unroll
            for (int j = 0; j < 4; j++)
                #pragma unroll
                for (int i = 0; i < 4; i++) { a1[j][i] = 0.f; a2[j][i] = 0.f; }
            #pragma unroll 8
            for (int e = 0; e < EE; e++) {
                const float4 w1 = *(const float4*)(Ws1 + e * AA + (ag << 2));
                const float4 w2 = *(const float4*)(Ws2 + e * AA + (ag << 2));
                const float4 xt = *(const float4*)(&xb[e][tg << 2]);
                const float xv[4] = {xt.x, xt.y, xt.z, xt.w};
                const float w1v[4] = {w1.x, w1.y, w1.z, w1.w};
                const float w2v[4] = {w2.x, w2.y, w2.z, w2.w};
                #pragma unroll
                for (int j = 0; j < 4; j++)
                    #pragma unroll
                    for (int i = 0; i < 4; i++) {
                        a1[j][i] = fmaf(xv[j], w1v[i], a1[j][i]);
                        a2[j][i] = fmaf(xv[j], w2v[i], a2[j][i]);
                    }
            }
            #pragma unroll
            for (int j = 0; j < 4; j++) {
                const int ts = (tg << 2) + j;
                if (ts < np) {
                    const int tok = tlist[ts];
                    *(float4*)(g_q + (size_t)tok * AA + (ag << 2)) =
                        make_float4(a1[j][0], a1[j][1], a1[j][2], a1[j][3]);
                    *(float4*)(g_v + (size_t)tok * AA + (ag << 2)) =
                        make_float4(a2[j][0], a2[j][1], a2[j][2], a2[j][3]);
                }
            }
        } else {
            float a1[4][4];
            #pragma unroll
            for (int j = 0; j < 4; j++)
                #pragma unroll
                for (int i = 0; i < 4; i++) a1[j][i] = 0.f;
            #pragma unroll 8
            for (int e = 0; e < EE; e++) {
                const float4 w1 = *(const float4*)(Ws1 + e * AA + (ag << 2));
                const float4 xt = *(const float4*)(&xb[e][tg << 2]);
                const float xv[4] = {xt.x, xt.y, xt.z, xt.w};
                const float w1v[4] = {w1.x, w1.y, w1.z, w1.w};
                #pragma unroll
                for (int j = 0; j < 4; j++)
                    #pragma unroll
                    for (int i = 0; i < 4; i++)
                        a1[j][i] = fmaf(xv[j], w1v[i], a1[j][i]);
            }
            #pragma unroll
            for (int j = 0; j < 4; j++) {
                const int ts = (tg << 2) + j;
                if (ts < np) {
                    const int tok = tlist[ts];
                    *(float4*)(g_k + (size_t)tok * AA + (ag << 2)) =
                        make_float4(a1[j][0], a1[j][1], a1[j][2], a1[j][3]);
                }
            }
        }
    }
}

// ---- 4. attention + pooling + FFN per node ----------------------------------
__global__ __launch_bounds__(128) void k_attn(const float* __restrict__ ffn_w,
                                              const float* __restrict__ ffn_b,
                                              float* __restrict__ out) {
    const int n = blockIdx.x, tid = threadIdx.x;
    __shared__ float qs[TT][EE + 1];
    __shared__ float ks2[TT][EE + 1];
    __shared__ float vs2[TT][EE + 1];
    __shared__ float sc[TT][TT + 1];
    __shared__ float att0[TT];
    __shared__ float pooled[AA];

    const float4* gq = (const float4*)(g_q + (size_t)n * TT * AA);
    const float4* gk = (const float4*)(g_k + (size_t)n * TT * AA);
    const float4* gv = (const float4*)(g_v + (size_t)n * TT * AA);
    for (int i = tid; i < TT * AA / 4; i += 128) {
        const int row = i >> 4, c = (i & 15) << 2;
        float4 vq = gq[i]; qs[row][c]=vq.x; qs[row][c+1]=vq.y; qs[row][c+2]=vq.z; qs[row][c+3]=vq.w;
        float4 vk = gk[i]; ks2[row][c]=vk.x; ks2[row][c+1]=vk.y; ks2[row][c+2]=vk.z; ks2[row][c+3]=vk.w;
        float4 vv = gv[i]; vs2[row][c]=vv.x; vs2[row][c+1]=vv.y; vs2[row][c+2]=vv.z; vs2[row][c+3]=vv.w;
    }
    __syncthreads();

    // scores: each thread does 8 k-cols for one q-row
    {
        const int qr = tid >> 2, kc0 = (tid & 3) << 3;
        float a8[8];
        #pragma unroll
        for (int j = 0; j < 8; j++) a8[j] = 0.f;
        #pragma unroll 8
        for (int e = 0; e < EE; e++) {
            const float qv = qs[qr][e];
            #pragma unroll
            for (int j = 0; j < 8; j++) a8[j] = fmaf(qv, ks2[kc0 + j][e], a8[j]);
        }
        #pragma unroll
        for (int j = 0; j < 8; j++) sc[qr][kc0 + j] = a8[j] * 0.125f;
    }
    __syncthreads();

    // softmax over QUERY axis per k-column; only row 0 weight needed
    if (tid < TT) {
        const int kc = tid;
        float mx = -1e30f;
        #pragma unroll
        for (int q = 0; q < TT; q++) mx = fmaxf(mx, sc[q][kc]);
        float s = 0.f;
        #pragma unroll
        for (int q = 0; q < TT; q++) s += __expf(sc[q][kc] - mx);
        att0[kc] = __expf(sc[0][kc] - mx) / s;
    }
    __syncthreads();

    if (tid < AA) {
        float acc = 0.f;
        #pragma unroll
        for (int k = 0; k < TT; k++) acc = fmaf(att0[k], vs2[k][tid], acc);
        pooled[tid] = acc;
    }
    __syncthreads();

    if (tid < EE) {
        float acc = ffn_b[tid];
        #pragma unroll
        for (int a = 0; a < AA; a++) acc = fmaf(pooled[a], ffn_w[a * EE + tid], acc);
        out[n * EE + tid] = acc;
    }
}

extern "C" void kernel_launch(void* const* d_in, const int* in_sizes, int n_in,
                              void* d_out, int out_size) {
    const float* h            = (const float*)d_in[0];
    const float* msg          = (const float*)d_in[1];
    const int*   msg_type     = (const int*)  d_in[2];
    const int*   r_label_node = (const int*)  d_in[3];
    const int*   r_label_msg  = (const int*)  d_in[4];
    const float* W_self       = (const float*)d_in[5];
    const float* Q            = (const float*)d_in[6];
    const float* K            = (const float*)d_in[7];
    const float* V            = (const float*)d_in[8];
    const float* ffn_w        = (const float*)d_in[9];
    const float* ffn_b        = (const float*)d_in[10];
    float* out = (float*)d_out;

    k_self<<<NN / 16, 256>>>(h, W_self);
    k_zero<<<1, 256>>>();
    k_count<<<NTOK / 512, 512>>>(msg_type, r_label_node, r_label_msg);
    k_scan<<<1, 256>>>();
    k_scatter<<<NTOK / 512, 512>>>(msg_type, r_label_node, r_label_msg);
    k_proj<<<2 * NREL, 128>>>(msg, Q, K, V);
    k_attn<<<NN, 128>>>(ffn_w, ffn_b, out);
}

// round 3
// speedup vs baseline: 1.6520x; 1.6520x over previous
#include <cuda_runtime.h>
#include <cuda_bf16.h>

#define NN 512
#define TT 32
#define MMSG 31
#define EE 64
#define AA 64
#define NREL 201      // 200 relations + self-loop id 200
#define NTOK (NN*TT)  // 16384
#define PB 32         // tokens per projection chunk
#define CAP 1024      // max tokens per bin (self K-bin holds exactly 512)
#define CHUNKS 16     // grid.y of k_proj (16*32 = 512 tokens covered)

// ---- device scratch (no allocations allowed) ------------------------------
__device__ float g_self[NN * EE];            // h @ W_self
__device__ float g_q[NTOK * AA];
__device__ float g_k[NTOK * AA];
__device__ float g_v[NTOK * AA];
__device__ int   g_cur[2 * 256];             // bin cursors (== counts after scatter)
__device__ int   g_list[2 * 256 * CAP];      // bin b tokens at g_list[b*CAP + i]

__device__ __forceinline__ void token_rels(int t, const int* mt, const int* rln,
                                           const int* rlm, int& rqv, int& rk) {
    int n = t >> 5, m = t & 31;
    if (m == 0) { rqv = rln[n]; rk = 200; }
    else { int i = n * MMSG + m - 1; rqv = rlm[i]; rk = mt[i]; }
}

// ---- 1. self projection + cursor zeroing ------------------------------------
__global__ __launch_bounds__(256) void k_self(const float* __restrict__ h,
                                              const float* __restrict__ W_self) {
    if (blockIdx.x == 0) {
        int i = threadIdx.x;
        g_cur[i] = 0; g_cur[256 + i] = 0;
    }
    __shared__ float Ws[EE * EE];
    __shared__ float hb[16][EE];
    const int tid = threadIdx.x;
    const int n0 = blockIdx.x * 16;
    for (int i = tid; i < EE * EE / 4; i += 256)
        ((float4*)Ws)[i] = ((const float4*)W_self)[i];
    for (int i = tid; i < 16 * EE / 4; i += 256)
        ((float4*)&hb[0][0])[i] = ((const float4*)(h + n0 * EE))[i];
    __syncthreads();
    const int a = tid & 63, ng = tid >> 6;
    #pragma unroll
    for (int s = 0; s < 4; s++) {
        const int nl = ng + s * 4;
        float acc = 0.f;
        #pragma unroll
        for (int e = 0; e < EE; e++) acc = fmaf(hb[nl][e], Ws[e * EE + a], acc);
        g_self[(n0 + nl) * EE + a] = acc;
    }
}

// ---- 2. scatter tokens into fixed-capacity bins ------------------------------
__global__ void k_scatter(const int* __restrict__ mt, const int* __restrict__ rln,
                          const int* __restrict__ rlm) {
    int t = blockIdx.x * 512 + threadIdx.x;
    int rqv, rk; token_rels(t, mt, rln, rlm, rqv, rk);
    int p0 = atomicAdd(&g_cur[rqv], 1);
    g_list[rqv * CAP + p0] = t;
    int p1 = atomicAdd(&g_cur[256 + rk], 1);
    g_list[(256 + rk) * CAP + p1] = t;
}

// ---- 3. bucketed relation projections ----------------------------------------
// blockIdx.x < 201: QV bucket (Q[r], V[r]); else K bucket. blockIdx.y = chunk.
__global__ __launch_bounds__(128) void k_proj(const float* __restrict__ msg,
                                              const float* __restrict__ Q,
                                              const float* __restrict__ K,
                                              const float* __restrict__ V) {
    const bool isK = blockIdx.x >= NREL;
    const int  r   = isK ? blockIdx.x - NREL : blockIdx.x;
    const int  bin = (isK ? 256 : 0) + r;
    const int  cnt = g_cur[bin];
    if ((int)blockIdx.y * PB >= cnt) return;

    __shared__ float Ws1[EE * AA];
    __shared__ float Ws2[EE * AA];
    __shared__ float xb[EE][PB];
    __shared__ int   tlist[PB];

    const int tid = threadIdx.x;
    const int* __restrict__ list = g_list + bin * CAP;

    // stage weights once per CTA
    {
        const float4* w1 = (const float4*)((isK ? K : Q) + (size_t)r * EE * AA);
        for (int i = tid; i < EE * AA / 4; i += 128) ((float4*)Ws1)[i] = w1[i];
        if (!isK) {
            const float4* w2 = (const float4*)(V + (size_t)r * EE * AA);
            for (int i = tid; i < EE * AA / 4; i += 128) ((float4*)Ws2)[i] = w2[i];
        }
    }

    const int ag = tid & 15;    // a-column group: a = ag*4
    const int tg = tid >> 4;    // token group: tokens tg*4 .. tg*4+3

    for (int c = blockIdx.y; c * PB < cnt; c += gridDim.y) {
        const int p  = c * PB;
        const int np = min(PB, cnt - p);
        __syncthreads();
        // stage x transposed into xb[e][tt]
        {
            const int tt = tid >> 2, qq = tid & 3;
            const bool valid = tt < np;
            int tok = valid ? list[p + tt] : 0;
            if (qq == 0) tlist[tt] = tok;
            const int n = tok >> 5, m = tok & 31;
            const float* xp = (m == 0) ? (g_self + n * EE)
                                       : (msg + (size_t)(n * MMSG + m - 1) * EE);
            #pragma unroll
            for (int j = 0; j < 4; j++) {
                const int e = qq * 16 + j * 4;
                float4 xv = valid ? *(const float4*)(xp + e) : make_float4(0.f,0.f,0.f,0.f);
                xb[e + 0][tt] = xv.x; xb[e + 1][tt] = xv.y;
                xb[e + 2][tt] = xv.z; xb[e + 3][tt] = xv.w;
            }
        }
        __syncthreads();

        if (!isK) {
            float a1[4][4], a2[4][4];
            #pragma unroll
            for (int j = 0; j < 4; j++)
                #pragma unroll
                for (int i = 0; i < 4; i++) { a1[j][i] = 0.f; a2[j][i] = 0.f; }
            #pragma unroll 8
            for (int e = 0; e < EE; e++) {
                const float4 w1 = *(const float4*)(Ws1 + e * AA + (ag << 2));
                const float4 w2 = *(const float4*)(Ws2 + e * AA + (ag << 2));
                const float4 xt = *(const float4*)(&xb[e][tg << 2]);
                const float xv[4]  = {xt.x, xt.y, xt.z, xt.w};
                const float w1v[4] = {w1.x, w1.y, w1.z, w1.w};
                const float w2v[4] = {w2.x, w2.y, w2.z, w2.w};
                #pragma unroll
                for (int j = 0; j < 4; j++)
                    #pragma unroll
                    for (int i = 0; i < 4; i++) {
                        a1[j][i] = fmaf(xv[j], w1v[i], a1[j][i]);
                        a2[j][i] = fmaf(xv[j], w2v[i], a2[j][i]);
                    }
            }
            #pragma unroll
            for (int j = 0; j < 4; j++) {
                const int ts = (tg << 2) + j;
                if (ts < np) {
                    const int tok = tlist[ts];
                    *(float4*)(g_q + (size_t)tok * AA + (ag << 2)) =
                        make_float4(a1[j][0], a1[j][1], a1[j][2], a1[j][3]);
                    *(float4*)(g_v + (size_t)tok * AA + (ag << 2)) =
                        make_float4(a2[j][0], a2[j][1], a2[j][2], a2[j][3]);
                }
            }
        } else {
            float a1[4][4];
            #pragma unroll
            for (int j = 0; j < 4; j++)
                #pragma unroll
                for (int i = 0; i < 4; i++) a1[j][i] = 0.f;
            #pragma unroll 8
            for (int e = 0; e < EE; e++) {
                const float4 w1 = *(const float4*)(Ws1 + e * AA + (ag << 2));
                const float4 xt = *(const float4*)(&xb[e][tg << 2]);
                const float xv[4]  = {xt.x, xt.y, xt.z, xt.w};
                const float w1v[4] = {w1.x, w1.y, w1.z, w1.w};
                #pragma unroll
                for (int j = 0; j < 4; j++)
                    #pragma unroll
                    for (int i = 0; i < 4; i++)
                        a1[j][i] = fmaf(xv[j], w1v[i], a1[j][i]);
            }
            #pragma unroll
            for (int j = 0; j < 4; j++) {
                const int ts = (tg << 2) + j;
                if (ts < np) {
                    const int tok = tlist[ts];
                    *(float4*)(g_k + (size_t)tok * AA + (ag << 2)) =
                        make_float4(a1[j][0], a1[j][1], a1[j][2], a1[j][3]);
                }
            }
        }
    }
}

// ---- 4. attention + pooling + FFN per node ----------------------------------
__global__ __launch_bounds__(128) void k_attn(const float* __restrict__ ffn_w,
                                              const float* __restrict__ ffn_b,
                                              float* __restrict__ out) {
    const int n = blockIdx.x, tid = threadIdx.x;
    __shared__ float qs[TT][EE + 1];
    __shared__ float ks2[TT][EE + 1];
    __shared__ float vs2[TT][EE + 1];
    __shared__ float sc[TT][TT + 1];
    __shared__ float att0[TT];
    __shared__ float pooled[AA];

    const float4* gq = (const float4*)(g_q + (size_t)n * TT * AA);
    const float4* gk = (const float4*)(g_k + (size_t)n * TT * AA);
    const float4* gv = (const float4*)(g_v + (size_t)n * TT * AA);
    for (int i = tid; i < TT * AA / 4; i += 128) {
        const int row = i >> 4, c = (i & 15) << 2;
        float4 vq = gq[i]; qs[row][c]=vq.x; qs[row][c+1]=vq.y; qs[row][c+2]=vq.z; qs[row][c+3]=vq.w;
        float4 vk = gk[i]; ks2[row][c]=vk.x; ks2[row][c+1]=vk.y; ks2[row][c+2]=vk.z; ks2[row][c+3]=vk.w;
        float4 vv = gv[i]; vs2[row][c]=vv.x; vs2[row][c+1]=vv.y; vs2[row][c+2]=vv.z; vs2[row][c+3]=vv.w;
    }
    __syncthreads();

    {
        const int qr = tid >> 2, kc0 = (tid & 3) << 3;
        float a8[8];
        #pragma unroll
        for (int j = 0; j < 8; j++) a8[j] = 0.f;
        #pragma unroll 8
        for (int e = 0; e < EE; e++) {
            const float qv = qs[qr][e];
            #pragma unroll
            for (int j = 0; j < 8; j++) a8[j] = fmaf(qv, ks2[kc0 + j][e], a8[j]);
        }
        #pragma unroll
        for (int j = 0; j < 8; j++) sc[qr][kc0 + j] = a8[j] * 0.125f;
    }
    __syncthreads();

    if (tid < TT) {
        const int kc = tid;
        float mx = -1e30f;
        #pragma unroll
        for (int q = 0; q < TT; q++) mx = fmaxf(mx, sc[q][kc]);
        float s = 0.f;
        #pragma unroll
        for (int q = 0; q < TT; q++) s += __expf(sc[q][kc] - mx);
        att0[kc] = __expf(sc[0][kc] - mx) / s;
    }
    __syncthreads();

    if (tid < AA) {
        float acc = 0.f;
        #pragma unroll
        for (int k = 0; k < TT; k++) acc = fmaf(att0[k], vs2[k][tid], acc);
        pooled[tid] = acc;
    }
    __syncthreads();

    if (tid < EE) {
        float acc = ffn_b[tid];
        #pragma unroll
        for (int a = 0; a < AA; a++) acc = fmaf(pooled[a], ffn_w[a * EE + tid], acc);
        out[n * EE + tid] = acc;
    }
}

extern "C" void kernel_launch(void* const* d_in, const int* in_sizes, int n_in,
                              void* d_out, int out_size) {
    const float* h            = (const float*)d_in[0];
    const float* msg          = (const float*)d_in[1];
    const int*   msg_type     = (const int*)  d_in[2];
    const int*   r_label_node = (const int*)  d_in[3];
    const int*   r_label_msg  = (const int*)  d_in[4];
    const float* W_self       = (const float*)d_in[5];
    const float* Q            = (const float*)d_in[6];
    const float* K            = (const float*)d_in[7];
    const float* V            = (const float*)d_in[8];
    const float* ffn_w        = (const float*)d_in[9];
    const float* ffn_b        = (const float*)d_in[10];
    float* out = (float*)d_out;

    k_self<<<NN / 16, 256>>>(h, W_self);
    k_scatter<<<NTOK / 512, 512>>>(msg_type, r_label_node, r_label_msg);
    dim3 pg(2 * NREL, CHUNKS);
    k_proj<<<pg, 128>>>(msg, Q, K, V);
    k_attn<<<NN, 128>>>(ffn_w, ffn_b, out);
}